// round 10
// baseline (speedup 1.0000x reference)
#include <cuda_runtime.h>
#include <cstdint>

// Problem constants
#define NB 4
#define NN 4096
#define NV 2048
#define NP 32
// channel layout: c_off = {0,16,64,144}, total 256
// y rows: y_off = {0,4,13,23}, total 30
// output widths: W = {160, 336, 384, 320}
// output offsets (elements): 0, 1310720, 9568256, 25296896

// ---------------- CG tables (device-precomputed each launch) ----------------
__device__ int  d_nnz[64][7];
__device__ int2 d_voff[64][7][49];   // {smem offset, float bits}

struct cplx { double re, im; };
__device__ __forceinline__ cplx cmul(cplx a, cplx b) {
    return { a.re * b.re - a.im * b.im, a.re * b.im + a.im * b.re };
}

__device__ double dfact(int n) { double r = 1.0; for (int i = 2; i <= n; i++) r *= i; return r; }

__device__ double su2cg(int j1, int m1, int j2, int m2, int j3, int m3) {
    if (m3 != m1 + m2) return 0.0;
    int vmin = max(max(-j1 + j2 + m3, -j1 + m1), 0);
    int vmax = min(min(j2 + j3 + m1, j3 - j1 + j2), j3 + m3);
    double C = sqrt((2.0 * j3 + 1.0) * dfact(j3 + j1 - j2) * dfact(j3 - j1 + j2) * dfact(j1 + j2 - j3)
                    * dfact(j3 + m3) * dfact(j3 - m3)
                    / (dfact(j1 + j2 + j3 + 1) * dfact(j1 - m1) * dfact(j1 + m1)
                       * dfact(j2 - m2) * dfact(j2 + m2)));
    double S = 0.0;
    for (int v = vmin; v <= vmax; v++) {
        double sgn = ((v + j2 + m2) & 1) ? -1.0 : 1.0;
        S += sgn * dfact(j2 + j3 + m1 - v) * dfact(j1 - m1 + v)
             / (dfact(v) * dfact(j3 - j1 + j2 - v) * dfact(j3 + m3 - v) * dfact(v + j1 - j2 - m3));
    }
    return C * S;
}

// Q_{real->complex}(l)[r][c], includes the (-i)^l phase
__device__ cplx qel(int l, int r, int c) {
    int m = r - l;
    const double s2 = 0.70710678118654752440;
    double re = 0, im = 0;
    if (m == 0) { if (c == l) re = 1.0; }
    else if (m < 0) {
        if (c == 2 * l - r) re = s2;        // col l+|m|
        else if (c == r)    im = -s2;       // col l-|m|
    } else {
        double sgn = (m & 1) ? -1.0 : 1.0;
        if (c == r)             re = sgn * s2;   // col l+m
        else if (c == 2 * l - r) im = sgn * s2;  // col l-m
    }
    cplx v{re, im};
    switch (l & 3) {  // multiply by (-i)^l
        case 1:  return {  v.im, -v.re };
        case 2:  return { -v.re, -v.im };
        case 3:  return { -v.im,  v.re };
        default: return v;
    }
}

__global__ void cg_precompute_kernel() {
    int bid = blockIdx.x;
    int j = (bid >> 4) & 3, l = (bid >> 2) & 3, J = bid & 3;
    int lo = (j > l) ? j - l : l - j;
    int hi = (j + l > 3) ? 3 : (j + l);
    if (j < 1 || l < 1 || J < lo || J > hi) return;

    __shared__ double cgs[7][7];
    __shared__ double creal[7][7][7];
    int tid = threadIdx.x;
    int nj = 2 * j + 1, nl = 2 * l + 1, nJ = 2 * J + 1;

    if (tid < nj * nl) {
        int i = tid / nl, k = tid - i * nl;
        int m1 = i - j, m2 = k - l, m3 = m1 + m2;
        cgs[i][k] = (m3 >= -J && m3 <= J) ? su2cg(j, m1, l, m2, J, m3) : 0.0;
    }
    __syncthreads();

    int tot = nj * nl * nJ;
    if (tid < tot) {
        int p = tid % nJ; int t2 = tid / nJ;
        int b = t2 % nl;  int a = t2 / nl;
        double acc = 0.0;
        for (int i = 0; i < nj; i++)
            for (int k = 0; k < nl; k++) {
                double c = cgs[i][k];
                if (c == 0.0) continue;
                int n = (i - j) + (k - l) + J;          // complex m3 index in J block
                cplx t = cmul(qel(j, i, a), qel(l, k, b));
                cplx q3 = qel(J, n, p); q3.im = -q3.im; // conj
                t = cmul(t, q3);
                acc += t.re * c;
            }
        creal[a][b][p] = acc;
    }
    __syncthreads();

    const int yoff[4] = {0, 4, 13, 23};
    const int coff[4] = {0, 16, 64, 144};
    if (tid < nJ) {
        int pid = j * 16 + l * 4 + J;
        int cnt = 0;
        for (int a = 0; a < nj; a++)
            for (int b = 0; b < nl; b++) {
                double v = creal[a][b][tid];
                if (fabs(v) > 1e-9) {
                    // smem element offset of Y[y_off[j]+a*(4-j) (+i)][c_off[l]+b*16 (+cc)]
                    int off = (yoff[j] + a * (4 - j)) * 256 + coff[l] + b * 16;
                    d_voff[pid][tid][cnt] = make_int2(off, __float_as_int((float)v));
                    cnt++;
                }
            }
        d_nnz[pid][tid] = cnt;
    }
}

// ---------------- packed f32x2 helpers ----------------
__device__ __forceinline__ unsigned long long pack2(float x) {
    unsigned long long r; unsigned u = __float_as_uint(x);
    asm("mov.b64 %0, {%1, %1};" : "=l"(r) : "r"(u));
    return r;
}
__device__ __forceinline__ unsigned long long fma2(unsigned long long a, unsigned long long b,
                                                   unsigned long long c) {
    unsigned long long d;
    asm("fma.rn.f32x2 %0, %1, %2, %3;" : "=l"(d) : "l"(a), "l"(b), "l"(c));
    return d;
}
__device__ __forceinline__ void unpack2(unsigned long long v, float& x, float& y) {
    unsigned a, b;
    asm("mov.b64 {%0, %1}, %2;" : "=r"(a), "=r"(b) : "l"(v));
    x = __uint_as_float(a); y = __uint_as_float(b);
}

#define THREADS 256

// ---------------- stage-3 building blocks ----------------
// l==0 copy: out[j] block at channel 0: [n][i*16+cc] = Y[y_off[j]+n*(4-j)+i][cc]
template<int j, int W>
__device__ __forceinline__ void copy_l0(const float* Y, float* oJ, int tid) {
    constexpr int yo  = (j == 0 ? 0 : (j == 1 ? 4 : (j == 2 ? 13 : 23)));
    constexpr int nim = 4 - j;
    constexpr int nq  = (2 * j + 1) * nim * 4;   // float4 count
    for (int e = tid; e < nq; e += THREADS) {
        int n = e / (nim * 4);
        int r = e - n * (nim * 4);
        int i = r >> 2, q = r & 3;
        float4 v = *(const float4*)&Y[(yo + n * nim + i) * 256 + q * 4];
        *(float4*)&oJ[n * W + i * 16 + q * 4] = v;
    }
}
// j==0 copy: out[l] block: [m][i*16+cc] = Y[i][c_off[l]+m*16+cc]   (i in 0..3)
template<int l, int W, int CHOFF>
__device__ __forceinline__ void copy_j0(const float* Y, float* oJ, int tid) {
    constexpr int co = (l == 1 ? 16 : (l == 2 ? 64 : 144));
    constexpr int nq = (2 * l + 1) * 16;
    for (int e = tid; e < nq; e += THREADS) {
        int m = e >> 4, r = e & 15, i = r >> 2, q = r & 3;
        float4 v = *(const float4*)&Y[i * 256 + co + m * 16 + q * 4];
        *(float4*)&oJ[m * W + CHOFF + i * 16 + q * 4] = v;
    }
}
// CG block: out[pJ][i*16+cc] = sum_{n,m} C[n][m][pJ] * Y[y_off[j]+n*(4-j)+i][c_off[l]+m*16+cc]
template<int j, int l, int J, int CHOFF, int W>
__device__ __forceinline__ void cg_block(const float* Y, float* oJ, int tid) {
    constexpr int pid  = j * 16 + l * 4 + J;
    constexpr int half = (4 - j) * 8;            // float2 elements per pJ row
    constexpr int ne   = (2 * J + 1) * half;
    for (int e = tid; e < ne; e += THREADS) {
        int pJ = e / half;
        int r  = e - pJ * half;
        int add = (r >> 3) * 256 + (r & 7) * 2;  // i*256 + cc2*2
        int nnz = d_nnz[pid][pJ];
        float ax = 0.f, ay = 0.f;
        for (int k = 0; k < nnz; k++) {
            int2 vo = d_voff[pid][pJ][k];
            float vv = __int_as_float(vo.y);
            float2 yv = *(const float2*)(Y + vo.x + add);
            ax = fmaf(vv, yv.x, ax);
            ay = fmaf(vv, yv.y, ay);
        }
        *(float2*)&oJ[pJ * W + CHOFF + (r >> 3) * 16 + (r & 7) * 2] = make_float2(ax, ay);
    }
}

// ---------------- main kernel: one CTA per (b,v), 256 threads ----------------
__global__ void __launch_bounds__(THREADS, 4) shconv_kernel(
    const float* __restrict__ x0, const float* __restrict__ x1,
    const float* __restrict__ x2, const float* __restrict__ x3,
    const int* __restrict__ pidx, const float* __restrict__ kern,
    float* __restrict__ out)
{
    __shared__ __align__(16) float Ksm[32 * 32];    // K rows padded 30 -> 32
    __shared__ __align__(16) float Gsm[32 * 256];   // reused as Y[30][256]
    __shared__ int rowid[32];

    int tid = threadIdx.x;
    int bv  = blockIdx.x;

    if (tid < 32) {
        int2 pi = ((const int2*)pidx)[(size_t)bv * 32 + tid];
        rowid[tid] = pi.x * NN + pi.y;
    }
    const float* kb = kern + (size_t)bv * 960;
    for (int i = tid; i < 960; i += THREADS) {
        int r = i / 30, c = i - r * 30;
        Ksm[r * 32 + c] = kb[i];
    }
    __syncthreads();

    // gather G: 32 rows x 256 floats = 2048 float4
    for (int e = tid; e < 2048; e += THREADS) {
        int p = e >> 6, f = e & 63;
        size_t r = (size_t)rowid[p];
        float4 v;
        if (f < 4)       v = ((const float4*)x0)[r * 4  + f];
        else if (f < 16) v = ((const float4*)x1)[r * 12 + (f - 4)];
        else if (f < 36) v = ((const float4*)x2)[r * 20 + (f - 16)];
        else             v = ((const float4*)x3)[r * 28 + (f - 36)];
        ((float4*)Gsm)[p * 64 + f] = v;
    }
    __syncthreads();

    // stage 1: Y(30x256) = K(32x30)^T G(32x256); thread owns column tid,
    // 15 row-pair f32x2 accumulators; K rows read as 8x LDS.128
    unsigned long long acc[15];
#pragma unroll
    for (int rp = 0; rp < 15; rp++) acc[rp] = 0ull;

    const float* gcol = Gsm + tid;
#pragma unroll 2
    for (int p = 0; p < 32; p++) {
        float gv = gcol[p * 256];
        unsigned long long gg = pack2(gv);
        const ulonglong2* kr = (const ulonglong2*)(Ksm + p * 32);
#pragma unroll
        for (int m = 0; m < 7; m++) {
            ulonglong2 kk = kr[m];                 // rows 4m..4m+3 as two pairs
            acc[2 * m]     = fma2(kk.x, gg, acc[2 * m]);
            acc[2 * m + 1] = fma2(kk.y, gg, acc[2 * m + 1]);
        }
        ulonglong2 kt = kr[7];                     // rows 28,29 (pad 30,31 unused)
        acc[14] = fma2(kt.x, gg, acc[14]);
    }
    __syncthreads();   // everyone done reading Gsm

    // write Y into Gsm
#pragma unroll
    for (int rp = 0; rp < 15; rp++) {
        float a0, a1;
        unpack2(acc[rp], a0, a1);
        Gsm[(2 * rp)     * 256 + tid] = a0;
        Gsm[(2 * rp + 1) * 256 + tid] = a1;
    }
    __syncthreads();

    // stage 3: assemble outputs
    const float* Y = Gsm;
    float* o0 = out +               (size_t)bv * 160;
    float* o1 = out + 1310720u  +   (size_t)bv * 1008;   // 3*336
    float* o2 = out + 9568256u  +   (size_t)bv * 1920;   // 5*384
    float* o3 = out + 25296896u +   (size_t)bv * 2240;   // 7*320

    // direct copies
    copy_l0<0, 160>(Y, o0, tid);
    copy_l0<1, 336>(Y, o1, tid);
    copy_j0<1, 336, 48>(Y, o1, tid);
    copy_l0<2, 384>(Y, o2, tid);
    copy_j0<2, 384, 32>(Y, o2, tid);
    copy_l0<3, 320>(Y, o3, tid);
    copy_j0<3, 320, 16>(Y, o3, tid);

    // CG blocks (order/offsets match reference concatenation)
    // J = 0, W = 160
    cg_block<1, 1, 0,  64, 160>(Y, o0, tid);
    cg_block<2, 2, 0, 112, 160>(Y, o0, tid);
    cg_block<3, 3, 0, 144, 160>(Y, o0, tid);
    // J = 1, W = 336
    cg_block<1, 1, 1, 112, 336>(Y, o1, tid);
    cg_block<2, 1, 1, 160, 336>(Y, o1, tid);
    cg_block<1, 2, 1, 192, 336>(Y, o1, tid);
    cg_block<2, 2, 1, 240, 336>(Y, o1, tid);
    cg_block<3, 2, 1, 272, 336>(Y, o1, tid);
    cg_block<2, 3, 1, 288, 336>(Y, o1, tid);
    cg_block<3, 3, 1, 320, 336>(Y, o1, tid);
    // J = 2, W = 384
    cg_block<1, 1, 2,  96, 384>(Y, o2, tid);
    cg_block<2, 1, 2, 144, 384>(Y, o2, tid);
    cg_block<3, 1, 2, 176, 384>(Y, o2, tid);
    cg_block<1, 2, 2, 192, 384>(Y, o2, tid);
    cg_block<2, 2, 2, 240, 384>(Y, o2, tid);
    cg_block<3, 2, 2, 272, 384>(Y, o2, tid);
    cg_block<1, 3, 2, 288, 384>(Y, o2, tid);
    cg_block<2, 3, 2, 336, 384>(Y, o2, tid);
    cg_block<3, 3, 2, 368, 384>(Y, o2, tid);
    // J = 3, W = 320
    cg_block<2, 1, 3,  80, 320>(Y, o3, tid);
    cg_block<3, 1, 3, 112, 320>(Y, o3, tid);
    cg_block<1, 2, 3, 128, 320>(Y, o3, tid);
    cg_block<2, 2, 3, 176, 320>(Y, o3, tid);
    cg_block<3, 2, 3, 208, 320>(Y, o3, tid);
    cg_block<1, 3, 3, 224, 320>(Y, o3, tid);
    cg_block<2, 3, 3, 272, 320>(Y, o3, tid);
    cg_block<3, 3, 3, 304, 320>(Y, o3, tid);
}

extern "C" void kernel_launch(void* const* d_in, const int* in_sizes, int n_in,
                              void* d_out, int out_size) {
    const float* x0   = (const float*)d_in[0];
    const float* x1   = (const float*)d_in[1];
    const float* x2   = (const float*)d_in[2];
    const float* x3   = (const float*)d_in[3];
    const int*   pidx = (const int*)d_in[4];
    const float* kern = (const float*)d_in[5];
    float* out = (float*)d_out;

    cg_precompute_kernel<<<64, 343>>>();
    shconv_kernel<<<NB * NV, THREADS>>>(x0, x1, x2, x3, pidx, kern, out);
}

// round 11
// speedup vs baseline: 1.2701x; 1.2701x over previous
#include <cuda_runtime.h>
#include <cstdint>

// Problem constants
#define NB 4
#define NN 4096
#define NV 2048
#define NP 32
// channel layout: c_off = {0,16,64,144}, total 256
// y rows: y_off = {0,4,13,23}, total 30
// output widths: W = {160, 336, 384, 320}
// output offsets (elements): 0, 1310720, 9568256, 25296896

// ---------------- CG tables (device-precomputed each launch, fp32) ----------------
__device__ int  d_nnz[64][7];
__device__ int2 d_voff[64][7][49];   // {smem offset, float bits}

struct cplxf { float re, im; };
__device__ __forceinline__ cplxf cmulf(cplxf a, cplxf b) {
    return { a.re * b.re - a.im * b.im, a.re * b.im + a.im * b.re };
}

__device__ float dfact_f(int n) { float r = 1.0f; for (int i = 2; i <= n; i++) r *= (float)i; return r; }

__device__ float su2cg_f(int j1, int m1, int j2, int m2, int j3, int m3) {
    if (m3 != m1 + m2) return 0.0f;
    int vmin = max(max(-j1 + j2 + m3, -j1 + m1), 0);
    int vmax = min(min(j2 + j3 + m1, j3 - j1 + j2), j3 + m3);
    float C = sqrtf((2.0f * j3 + 1.0f) * dfact_f(j3 + j1 - j2) * dfact_f(j3 - j1 + j2) * dfact_f(j1 + j2 - j3)
                    * dfact_f(j3 + m3) * dfact_f(j3 - m3)
                    / (dfact_f(j1 + j2 + j3 + 1) * dfact_f(j1 - m1) * dfact_f(j1 + m1)
                       * dfact_f(j2 - m2) * dfact_f(j2 + m2)));
    float S = 0.0f;
    for (int v = vmin; v <= vmax; v++) {
        float sgn = ((v + j2 + m2) & 1) ? -1.0f : 1.0f;
        S += sgn * dfact_f(j2 + j3 + m1 - v) * dfact_f(j1 - m1 + v)
             / (dfact_f(v) * dfact_f(j3 - j1 + j2 - v) * dfact_f(j3 + m3 - v) * dfact_f(v + j1 - j2 - m3));
    }
    return C * S;
}

// Q_{real->complex}(l)[r][c], includes the (-i)^l phase
__device__ cplxf qel_f(int l, int r, int c) {
    int m = r - l;
    const float s2 = 0.70710678118654752440f;
    float re = 0.f, im = 0.f;
    if (m == 0) { if (c == l) re = 1.0f; }
    else if (m < 0) {
        if (c == 2 * l - r) re = s2;        // col l+|m|
        else if (c == r)    im = -s2;       // col l-|m|
    } else {
        float sgn = (m & 1) ? -1.0f : 1.0f;
        if (c == r)             re = sgn * s2;   // col l+m
        else if (c == 2 * l - r) im = sgn * s2;  // col l-m
    }
    cplxf v{re, im};
    switch (l & 3) {  // multiply by (-i)^l
        case 1:  return {  v.im, -v.re };
        case 2:  return { -v.re, -v.im };
        case 3:  return { -v.im,  v.re };
        default: return v;
    }
}

__global__ void cg_precompute_kernel() {
    int bid = blockIdx.x;
    int j = (bid >> 4) & 3, l = (bid >> 2) & 3, J = bid & 3;
    int lo = (j > l) ? j - l : l - j;
    int hi = (j + l > 3) ? 3 : (j + l);
    if (j < 1 || l < 1 || J < lo || J > hi) return;

    __shared__ float cgs[7][7];
    __shared__ float creal[7][7][7];
    int tid = threadIdx.x;
    int nj = 2 * j + 1, nl = 2 * l + 1, nJ = 2 * J + 1;

    if (tid < nj * nl) {
        int i = tid / nl, k = tid - i * nl;
        int m1 = i - j, m2 = k - l, m3 = m1 + m2;
        cgs[i][k] = (m3 >= -J && m3 <= J) ? su2cg_f(j, m1, l, m2, J, m3) : 0.0f;
    }
    __syncthreads();

    int tot = nj * nl * nJ;
    if (tid < tot) {
        int p = tid % nJ; int t2 = tid / nJ;
        int b = t2 % nl;  int a = t2 / nl;
        float acc = 0.0f;
        for (int i = 0; i < nj; i++)
            for (int k = 0; k < nl; k++) {
                float c = cgs[i][k];
                if (c == 0.0f) continue;
                int n = (i - j) + (k - l) + J;          // complex m3 index in J block
                cplxf t = cmulf(qel_f(j, i, a), qel_f(l, k, b));
                cplxf q3 = qel_f(J, n, p); q3.im = -q3.im; // conj
                t = cmulf(t, q3);
                acc += t.re * c;
            }
        creal[a][b][p] = acc;
    }
    __syncthreads();

    const int yoff[4] = {0, 4, 13, 23};
    const int coff[4] = {0, 16, 64, 144};
    if (tid < nJ) {
        int pid = j * 16 + l * 4 + J;
        int cnt = 0;
        for (int a = 0; a < nj; a++)
            for (int b = 0; b < nl; b++) {
                float v = creal[a][b][tid];
                if (fabsf(v) > 1e-7f) {
                    // smem element offset of Y[y_off[j]+a*(4-j) (+i)][c_off[l]+b*16 (+cc)]
                    int off = (yoff[j] + a * (4 - j)) * 256 + coff[l] + b * 16;
                    d_voff[pid][tid][cnt] = make_int2(off, __float_as_int(v));
                    cnt++;
                }
            }
        d_nnz[pid][tid] = cnt;
    }
}

// ---------------- packed f32x2 helpers ----------------
__device__ __forceinline__ unsigned long long pack2(float x) {
    unsigned long long r; unsigned u = __float_as_uint(x);
    asm("mov.b64 %0, {%1, %1};" : "=l"(r) : "r"(u));
    return r;
}
__device__ __forceinline__ unsigned long long fma2(unsigned long long a, unsigned long long b,
                                                   unsigned long long c) {
    unsigned long long d;
    asm("fma.rn.f32x2 %0, %1, %2, %3;" : "=l"(d) : "l"(a), "l"(b), "l"(c));
    return d;
}
__device__ __forceinline__ void unpack2(unsigned long long v, float& x, float& y) {
    unsigned a, b;
    asm("mov.b64 {%0, %1}, %2;" : "=r"(a), "=r"(b) : "l"(v));
    x = __uint_as_float(a); y = __uint_as_float(b);
}

#define THREADS 128

// ---------------- stage-3 building blocks ----------------
// l==0 copy: out[j] block at channel 0: [n][i*16+cc] = Y[y_off[j]+n*(4-j)+i][cc]
template<int j, int W>
__device__ __forceinline__ void copy_l0(const float* Y, float* oJ, int tid) {
    constexpr int yo  = (j == 0 ? 0 : (j == 1 ? 4 : (j == 2 ? 13 : 23)));
    constexpr int nim = 4 - j;
    constexpr int nq  = (2 * j + 1) * nim * 4;   // float4 count
    for (int e = tid; e < nq; e += THREADS) {
        int n = e / (nim * 4);
        int r = e - n * (nim * 4);
        int i = r >> 2, q = r & 3;
        float4 v = *(const float4*)&Y[(yo + n * nim + i) * 256 + q * 4];
        *(float4*)&oJ[n * W + i * 16 + q * 4] = v;
    }
}
// j==0 copy: out[l] block: [m][i*16+cc] = Y[i][c_off[l]+m*16+cc]   (i in 0..3)
template<int l, int W, int CHOFF>
__device__ __forceinline__ void copy_j0(const float* Y, float* oJ, int tid) {
    constexpr int co = (l == 1 ? 16 : (l == 2 ? 64 : 144));
    constexpr int nq = (2 * l + 1) * 16;
    for (int e = tid; e < nq; e += THREADS) {
        int m = e >> 4, r = e & 15, i = r >> 2, q = r & 3;
        float4 v = *(const float4*)&Y[i * 256 + co + m * 16 + q * 4];
        *(float4*)&oJ[m * W + CHOFF + i * 16 + q * 4] = v;
    }
}
// CG block: out[pJ][i*16+cc] = sum_{n,m} C[n][m][pJ] * Y[y_off[j]+n*(4-j)+i][c_off[l]+m*16+cc]
template<int j, int l, int J, int CHOFF, int W>
__device__ __forceinline__ void cg_block(const float* Y, float* oJ, int tid) {
    constexpr int pid  = j * 16 + l * 4 + J;
    constexpr int half = (4 - j) * 8;            // float2 elements per pJ row
    constexpr int ne   = (2 * J + 1) * half;
    for (int e = tid; e < ne; e += THREADS) {
        int pJ = e / half;
        int r  = e - pJ * half;
        int add = (r >> 3) * 256 + (r & 7) * 2;  // i*256 + cc2*2
        int nnz = d_nnz[pid][pJ];
        float ax = 0.f, ay = 0.f;
        for (int k = 0; k < nnz; k++) {
            int2 vo = d_voff[pid][pJ][k];
            float vv = __int_as_float(vo.y);
            float2 yv = *(const float2*)(Y + vo.x + add);
            ax = fmaf(vv, yv.x, ax);
            ay = fmaf(vv, yv.y, ay);
        }
        *(float2*)&oJ[pJ * W + CHOFF + (r >> 3) * 16 + (r & 7) * 2] = make_float2(ax, ay);
    }
}

// ---------------- main kernel: one CTA per (b,v), 128 threads, 6 CTAs/SM ----------------
__global__ void __launch_bounds__(THREADS, 6) shconv_kernel(
    const float* __restrict__ x0, const float* __restrict__ x1,
    const float* __restrict__ x2, const float* __restrict__ x3,
    const int* __restrict__ pidx, const float* __restrict__ kern,
    float* __restrict__ out)
{
    __shared__ __align__(16) float Ksm[32 * 32];    // K rows padded 30 -> 32
    __shared__ __align__(16) float Gsm[32 * 256];   // reused as Y[30][256]
    __shared__ int rowid[32];

    int tid = threadIdx.x;
    int bv  = blockIdx.x;

    if (tid < 32) {
        int2 pi = ((const int2*)pidx)[(size_t)bv * 32 + tid];
        rowid[tid] = pi.x * NN + pi.y;
    }
    const float* kb = kern + (size_t)bv * 960;
    for (int i = tid; i < 960; i += THREADS) {
        int r = i / 30, c = i - r * 30;
        Ksm[r * 32 + c] = kb[i];
    }
    __syncthreads();

    // gather G: 32 rows x 256 floats = 2048 float4
    for (int e = tid; e < 2048; e += THREADS) {
        int p = e >> 6, f = e & 63;
        size_t r = (size_t)rowid[p];
        float4 v;
        if (f < 4)       v = ((const float4*)x0)[r * 4  + f];
        else if (f < 16) v = ((const float4*)x1)[r * 12 + (f - 4)];
        else if (f < 36) v = ((const float4*)x2)[r * 20 + (f - 16)];
        else             v = ((const float4*)x3)[r * 28 + (f - 36)];
        ((float4*)Gsm)[p * 64 + f] = v;
    }
    __syncthreads();

    // stage 1: Y(30x256) = K(32x30)^T G(32x256), f32x2 row-pair packed
    // thread owns cols {2*tid, 2*tid+1}; K rows read as 8x LDS.128
    unsigned long long accA[15], accB[15];
#pragma unroll
    for (int rp = 0; rp < 15; rp++) { accA[rp] = 0ull; accB[rp] = 0ull; }

    const float2* gcol = (const float2*)Gsm + tid;
#pragma unroll 2
    for (int p = 0; p < 32; p++) {
        float2 g = gcol[p * 128];
        unsigned long long ga = pack2(g.x), gb = pack2(g.y);
        const ulonglong2* kr = (const ulonglong2*)(Ksm + p * 32);
#pragma unroll
        for (int m = 0; m < 7; m++) {
            ulonglong2 kk = kr[m];                 // row pairs (4m,4m+1) and (4m+2,4m+3)
            accA[2 * m]     = fma2(kk.x, ga, accA[2 * m]);
            accB[2 * m]     = fma2(kk.x, gb, accB[2 * m]);
            accA[2 * m + 1] = fma2(kk.y, ga, accA[2 * m + 1]);
            accB[2 * m + 1] = fma2(kk.y, gb, accB[2 * m + 1]);
        }
        ulonglong2 kt = kr[7];                     // rows 28,29 (pad 30,31 unused)
        accA[14] = fma2(kt.x, ga, accA[14]);
        accB[14] = fma2(kt.x, gb, accB[14]);
    }
    __syncthreads();   // everyone done reading Gsm

    // write Y into Gsm: row 2rp -> (loA, loB), row 2rp+1 -> (hiA, hiB)
#pragma unroll
    for (int rp = 0; rp < 15; rp++) {
        float a0, a1, b0, b1;
        unpack2(accA[rp], a0, a1);
        unpack2(accB[rp], b0, b1);
        *(float2*)&Gsm[(2 * rp)     * 256 + 2 * tid] = make_float2(a0, b0);
        *(float2*)&Gsm[(2 * rp + 1) * 256 + 2 * tid] = make_float2(a1, b1);
    }
    __syncthreads();

    // stage 3: assemble outputs
    const float* Y = Gsm;
    float* o0 = out +               (size_t)bv * 160;
    float* o1 = out + 1310720u  +   (size_t)bv * 1008;   // 3*336
    float* o2 = out + 9568256u  +   (size_t)bv * 1920;   // 5*384
    float* o3 = out + 25296896u +   (size_t)bv * 2240;   // 7*320

    // direct copies
    copy_l0<0, 160>(Y, o0, tid);
    copy_l0<1, 336>(Y, o1, tid);
    copy_j0<1, 336, 48>(Y, o1, tid);
    copy_l0<2, 384>(Y, o2, tid);
    copy_j0<2, 384, 32>(Y, o2, tid);
    copy_l0<3, 320>(Y, o3, tid);
    copy_j0<3, 320, 16>(Y, o3, tid);

    // CG blocks (order/offsets match reference concatenation)
    // J = 0, W = 160
    cg_block<1, 1, 0,  64, 160>(Y, o0, tid);
    cg_block<2, 2, 0, 112, 160>(Y, o0, tid);
    cg_block<3, 3, 0, 144, 160>(Y, o0, tid);
    // J = 1, W = 336
    cg_block<1, 1, 1, 112, 336>(Y, o1, tid);
    cg_block<2, 1, 1, 160, 336>(Y, o1, tid);
    cg_block<1, 2, 1, 192, 336>(Y, o1, tid);
    cg_block<2, 2, 1, 240, 336>(Y, o1, tid);
    cg_block<3, 2, 1, 272, 336>(Y, o1, tid);
    cg_block<2, 3, 1, 288, 336>(Y, o1, tid);
    cg_block<3, 3, 1, 320, 336>(Y, o1, tid);
    // J = 2, W = 384
    cg_block<1, 1, 2,  96, 384>(Y, o2, tid);
    cg_block<2, 1, 2, 144, 384>(Y, o2, tid);
    cg_block<3, 1, 2, 176, 384>(Y, o2, tid);
    cg_block<1, 2, 2, 192, 384>(Y, o2, tid);
    cg_block<2, 2, 2, 240, 384>(Y, o2, tid);
    cg_block<3, 2, 2, 272, 384>(Y, o2, tid);
    cg_block<1, 3, 2, 288, 384>(Y, o2, tid);
    cg_block<2, 3, 2, 336, 384>(Y, o2, tid);
    cg_block<3, 3, 2, 368, 384>(Y, o2, tid);
    // J = 3, W = 320
    cg_block<2, 1, 3,  80, 320>(Y, o3, tid);
    cg_block<3, 1, 3, 112, 320>(Y, o3, tid);
    cg_block<1, 2, 3, 128, 320>(Y, o3, tid);
    cg_block<2, 2, 3, 176, 320>(Y, o3, tid);
    cg_block<3, 2, 3, 208, 320>(Y, o3, tid);
    cg_block<1, 3, 3, 224, 320>(Y, o3, tid);
    cg_block<2, 3, 3, 272, 320>(Y, o3, tid);
    cg_block<3, 3, 3, 304, 320>(Y, o3, tid);
}

extern "C" void kernel_launch(void* const* d_in, const int* in_sizes, int n_in,
                              void* d_out, int out_size) {
    const float* x0   = (const float*)d_in[0];
    const float* x1   = (const float*)d_in[1];
    const float* x2   = (const float*)d_in[2];
    const float* x3   = (const float*)d_in[3];
    const int*   pidx = (const int*)d_in[4];
    const float* kern = (const float*)d_in[5];
    float* out = (float*)d_out;

    cg_precompute_kernel<<<64, 343>>>();
    shconv_kernel<<<NB * NV, THREADS>>>(x0, x1, x2, x3, pidx, kern, out);
}

// round 14
// speedup vs baseline: 1.8008x; 1.4178x over previous
#include <cuda_runtime.h>
#include <cstdint>

// Problem constants
#define NB 4
#define NN 4096
#define NV 2048
#define NP 32
// channel layout: c_off = {0,16,64,144}, total 256
// y rows: y_off = {0,4,13,23}, total 30
// output widths: W = {160, 336, 384, 320}
// output offsets (elements): 0, 1310720, 9568256, 25296896

// ---------------- CG tables (device-precomputed each launch, fp32) ----------------
// entries padded with {0,0} to a multiple of 4 so the kernel loop can unroll
__device__ int  d_nnz[64][7];
__device__ int2 d_voff[64][7][52];   // {smem offset, float bits}

struct cplxf { float re, im; };
__device__ __forceinline__ cplxf cmulf(cplxf a, cplxf b) {
    return { a.re * b.re - a.im * b.im, a.re * b.im + a.im * b.re };
}

__device__ float dfact_f(int n) { float r = 1.0f; for (int i = 2; i <= n; i++) r *= (float)i; return r; }

__device__ float su2cg_f(int j1, int m1, int j2, int m2, int j3, int m3) {
    if (m3 != m1 + m2) return 0.0f;
    int vmin = max(max(-j1 + j2 + m3, -j1 + m1), 0);
    int vmax = min(min(j2 + j3 + m1, j3 - j1 + j2), j3 + m3);
    float C = sqrtf((2.0f * j3 + 1.0f) * dfact_f(j3 + j1 - j2) * dfact_f(j3 - j1 + j2) * dfact_f(j1 + j2 - j3)
                    * dfact_f(j3 + m3) * dfact_f(j3 - m3)
                    / (dfact_f(j1 + j2 + j3 + 1) * dfact_f(j1 - m1) * dfact_f(j1 + m1)
                       * dfact_f(j2 - m2) * dfact_f(j2 + m2)));
    float S = 0.0f;
    for (int v = vmin; v <= vmax; v++) {
        float sgn = ((v + j2 + m2) & 1) ? -1.0f : 1.0f;
        S += sgn * dfact_f(j2 + j3 + m1 - v) * dfact_f(j1 - m1 + v)
             / (dfact_f(v) * dfact_f(j3 - j1 + j2 - v) * dfact_f(j3 + m3 - v) * dfact_f(v + j1 - j2 - m3));
    }
    return C * S;
}

// Q_{real->complex}(l)[r][c], includes the (-i)^l phase
__device__ cplxf qel_f(int l, int r, int c) {
    int m = r - l;
    const float s2 = 0.70710678118654752440f;
    float re = 0.f, im = 0.f;
    if (m == 0) { if (c == l) re = 1.0f; }
    else if (m < 0) {
        if (c == 2 * l - r) re = s2;        // col l+|m|
        else if (c == r)    im = -s2;       // col l-|m|
    } else {
        float sgn = (m & 1) ? -1.0f : 1.0f;
        if (c == r)             re = sgn * s2;   // col l+m
        else if (c == 2 * l - r) im = sgn * s2;  // col l-m
    }
    cplxf v{re, im};
    switch (l & 3) {  // multiply by (-i)^l
        case 1:  return {  v.im, -v.re };
        case 2:  return { -v.re, -v.im };
        case 3:  return { -v.im,  v.re };
        default: return v;
    }
}

__global__ void cg_precompute_kernel() {
    int bid = blockIdx.x;
    int j = (bid >> 4) & 3, l = (bid >> 2) & 3, J = bid & 3;
    int lo = (j > l) ? j - l : l - j;
    int hi = (j + l > 3) ? 3 : (j + l);
    if (j < 1 || l < 1 || J < lo || J > hi) return;

    __shared__ float cgs[7][7];
    __shared__ float creal[7][7][7];
    int tid = threadIdx.x;
    int nj = 2 * j + 1, nl = 2 * l + 1, nJ = 2 * J + 1;

    if (tid < nj * nl) {
        int i = tid / nl, k = tid - i * nl;
        int m1 = i - j, m2 = k - l, m3 = m1 + m2;
        cgs[i][k] = (m3 >= -J && m3 <= J) ? su2cg_f(j, m1, l, m2, J, m3) : 0.0f;
    }
    __syncthreads();

    int tot = nj * nl * nJ;
    if (tid < tot) {
        int p = tid % nJ; int t2 = tid / nJ;
        int b = t2 % nl;  int a = t2 / nl;
        float acc = 0.0f;
        for (int i = 0; i < nj; i++)
            for (int k = 0; k < nl; k++) {
                float c = cgs[i][k];
                if (c == 0.0f) continue;
                int n = (i - j) + (k - l) + J;          // complex m3 index in J block
                cplxf t = cmulf(qel_f(j, i, a), qel_f(l, k, b));
                cplxf q3 = qel_f(J, n, p); q3.im = -q3.im; // conj
                t = cmulf(t, q3);
                acc += t.re * c;
            }
        creal[a][b][p] = acc;
    }
    __syncthreads();

    const int yoff[4] = {0, 4, 13, 23};
    const int coff[4] = {0, 16, 64, 144};
    if (tid < nJ) {
        int pid = j * 16 + l * 4 + J;
        int cnt = 0;
        for (int a = 0; a < nj; a++)
            for (int b = 0; b < nl; b++) {
                float v = creal[a][b][tid];
                if (fabsf(v) > 1e-7f) {
                    // smem element offset of Y[y_off[j]+a*(4-j) (+i)][c_off[l]+b*16 (+cc)]
                    int off = (yoff[j] + a * (4 - j)) * 256 + coff[l] + b * 16;
                    d_voff[pid][tid][cnt] = make_int2(off, __float_as_int(v));
                    cnt++;
                }
            }
        // pad with {0, 0.0f} to a multiple of 4 (zero value contributes nothing;
        // offset 0 reads valid smem)
        while (cnt & 3) { d_voff[pid][tid][cnt] = make_int2(0, 0); cnt++; }
        d_nnz[pid][tid] = cnt;
    }
}

// ---------------- packed f32x2 helpers ----------------
__device__ __forceinline__ unsigned long long pack2(float x) {
    unsigned long long r; unsigned u = __float_as_uint(x);
    asm("mov.b64 %0, {%1, %1};" : "=l"(r) : "r"(u));
    return r;
}
__device__ __forceinline__ unsigned long long fma2(unsigned long long a, unsigned long long b,
                                                   unsigned long long c) {
    unsigned long long d;
    asm("fma.rn.f32x2 %0, %1, %2, %3;" : "=l"(d) : "l"(a), "l"(b), "l"(c));
    return d;
}
__device__ __forceinline__ void unpack2(unsigned long long v, float& x, float& y) {
    unsigned a, b;
    asm("mov.b64 {%0, %1}, %2;" : "=r"(a), "=r"(b) : "l"(v));
    x = __uint_as_float(a); y = __uint_as_float(b);
}

#define THREADS 128

// ---------------- stage-3 building blocks ----------------
// l==0 copy: out[j] block at channel 0: [n][i*16+cc] = Y[y_off[j]+n*(4-j)+i][cc]
template<int j, int W>
__device__ __forceinline__ void copy_l0(const float* Y, float* oJ, int tid) {
    constexpr int yo  = (j == 0 ? 0 : (j == 1 ? 4 : (j == 2 ? 13 : 23)));
    constexpr int nim = 4 - j;
    constexpr int nq  = (2 * j + 1) * nim * 4;   // float4 count
    for (int e = tid; e < nq; e += THREADS) {
        int n = e / (nim * 4);
        int r = e - n * (nim * 4);
        int i = r >> 2, q = r & 3;
        float4 v = *(const float4*)&Y[(yo + n * nim + i) * 256 + q * 4];
        *(float4*)&oJ[n * W + i * 16 + q * 4] = v;
    }
}
// j==0 copy: out[l] block: [m][i*16+cc] = Y[i][c_off[l]+m*16+cc]   (i in 0..3)
template<int l, int W, int CHOFF>
__device__ __forceinline__ void copy_j0(const float* Y, float* oJ, int tid) {
    constexpr int co = (l == 1 ? 16 : (l == 2 ? 64 : 144));
    constexpr int nq = (2 * l + 1) * 16;
    for (int e = tid; e < nq; e += THREADS) {
        int m = e >> 4, r = e & 15, i = r >> 2, q = r & 3;
        float4 v = *(const float4*)&Y[i * 256 + co + m * 16 + q * 4];
        *(float4*)&oJ[m * W + CHOFF + i * 16 + q * 4] = v;
    }
}
// CG block: out[pJ][i*16+cc] = sum_{n,m} C[n][m][pJ] * Y[y_off[j]+n*(4-j)+i][c_off[l]+m*16+cc]
template<int j, int l, int J, int CHOFF, int W>
__device__ __forceinline__ void cg_block(const float* Y, float* oJ, int tid) {
    constexpr int pid  = j * 16 + l * 4 + J;
    constexpr int half = (4 - j) * 8;            // float2 elements per pJ row
    constexpr int ne   = (2 * J + 1) * half;
    for (int e = tid; e < ne; e += THREADS) {
        int pJ = e / half;
        int r  = e - pJ * half;
        int add = (r >> 3) * 256 + (r & 7) * 2;  // i*256 + cc2*2
        int nnz = d_nnz[pid][pJ];                // multiple of 4 by construction
        const int2* tab = d_voff[pid][pJ];
        float ax = 0.f, ay = 0.f;
#pragma unroll 4
        for (int k = 0; k < nnz; k++) {
            int2 vo = tab[k];
            float vv = __int_as_float(vo.y);
            float2 yv = *(const float2*)(Y + vo.x + add);
            ax = fmaf(vv, yv.x, ax);
            ay = fmaf(vv, yv.y, ay);
        }
        *(float2*)&oJ[pJ * W + CHOFF + (r >> 3) * 16 + (r & 7) * 2] = make_float2(ax, ay);
    }
}

// ---------------- main kernel: one CTA per (b,v), 128 threads ----------------
__global__ void __launch_bounds__(THREADS) shconv_kernel(
    const float* __restrict__ x0, const float* __restrict__ x1,
    const float* __restrict__ x2, const float* __restrict__ x3,
    const int* __restrict__ pidx, const float* __restrict__ kern,
    float* __restrict__ out)
{
    __shared__ __align__(16) float Ksm[32 * 32];    // K rows padded 30 -> 32
    __shared__ __align__(16) float Gsm[32 * 256];   // reused as Y[30][256]
    __shared__ int rowid[32];

    int tid = threadIdx.x;
    int bv  = blockIdx.x;

    if (tid < 32) {
        int2 pi = ((const int2*)pidx)[(size_t)bv * 32 + tid];
        rowid[tid] = pi.x * NN + pi.y;
    }
    const float* kb = kern + (size_t)bv * 960;
    for (int i = tid; i < 960; i += THREADS) {
        int r = i / 30, c = i - r * 30;
        Ksm[r * 32 + c] = kb[i];
    }
    __syncthreads();

    // gather G: 32 rows x 256 floats = 2048 float4
    for (int e = tid; e < 2048; e += THREADS) {
        int p = e >> 6, f = e & 63;
        size_t r = (size_t)rowid[p];
        float4 v;
        if (f < 4)       v = ((const float4*)x0)[r * 4  + f];
        else if (f < 16) v = ((const float4*)x1)[r * 12 + (f - 4)];
        else if (f < 36) v = ((const float4*)x2)[r * 20 + (f - 16)];
        else             v = ((const float4*)x3)[r * 28 + (f - 36)];
        ((float4*)Gsm)[p * 64 + f] = v;
    }
    __syncthreads();

    // stage 1: Y(30x256) = K(32x30)^T G(32x256), f32x2 row-pair packed
    // thread owns cols {2*tid, 2*tid+1}; K rows read as 8x LDS.128
    unsigned long long accA[15], accB[15];
#pragma unroll
    for (int rp = 0; rp < 15; rp++) { accA[rp] = 0ull; accB[rp] = 0ull; }

    const float2* gcol = (const float2*)Gsm + tid;
#pragma unroll 2
    for (int p = 0; p < 32; p++) {
        float2 g = gcol[p * 128];
        unsigned long long ga = pack2(g.x), gb = pack2(g.y);
        const ulonglong2* kr = (const ulonglong2*)(Ksm + p * 32);
#pragma unroll
        for (int m = 0; m < 7; m++) {
            ulonglong2 kk = kr[m];                 // row pairs (4m,4m+1) and (4m+2,4m+3)
            accA[2 * m]     = fma2(kk.x, ga, accA[2 * m]);
            accB[2 * m]     = fma2(kk.x, gb, accB[2 * m]);
            accA[2 * m + 1] = fma2(kk.y, ga, accA[2 * m + 1]);
            accB[2 * m + 1] = fma2(kk.y, gb, accB[2 * m + 1]);
        }
        ulonglong2 kt = kr[7];                     // rows 28,29 (pad 30,31 unused)
        accA[14] = fma2(kt.x, ga, accA[14]);
        accB[14] = fma2(kt.x, gb, accB[14]);
    }
    __syncthreads();   // everyone done reading Gsm

    // write Y into Gsm: row 2rp -> (loA, loB), row 2rp+1 -> (hiA, hiB)
#pragma unroll
    for (int rp = 0; rp < 15; rp++) {
        float a0, a1, b0, b1;
        unpack2(accA[rp], a0, a1);
        unpack2(accB[rp], b0, b1);
        *(float2*)&Gsm[(2 * rp)     * 256 + 2 * tid] = make_float2(a0, b0);
        *(float2*)&Gsm[(2 * rp + 1) * 256 + 2 * tid] = make_float2(a1, b1);
    }
    __syncthreads();

    // stage 3: assemble outputs
    const float* Y = Gsm;
    float* o0 = out +               (size_t)bv * 160;
    float* o1 = out + 1310720u  +   (size_t)bv * 1008;   // 3*336
    float* o2 = out + 9568256u  +   (size_t)bv * 1920;   // 5*384
    float* o3 = out + 25296896u +   (size_t)bv * 2240;   // 7*320

    // direct copies
    copy_l0<0, 160>(Y, o0, tid);
    copy_l0<1, 336>(Y, o1, tid);
    copy_j0<1, 336, 48>(Y, o1, tid);
    copy_l0<2, 384>(Y, o2, tid);
    copy_j0<2, 384, 32>(Y, o2, tid);
    copy_l0<3, 320>(Y, o3, tid);
    copy_j0<3, 320, 16>(Y, o3, tid);

    // CG blocks (order/offsets match reference concatenation)
    // J = 0, W = 160
    cg_block<1, 1, 0,  64, 160>(Y, o0, tid);
    cg_block<2, 2, 0, 112, 160>(Y, o0, tid);
    cg_block<3, 3, 0, 144, 160>(Y, o0, tid);
    // J = 1, W = 336
    cg_block<1, 1, 1, 112, 336>(Y, o1, tid);
    cg_block<2, 1, 1, 160, 336>(Y, o1, tid);
    cg_block<1, 2, 1, 192, 336>(Y, o1, tid);
    cg_block<2, 2, 1, 240, 336>(Y, o1, tid);
    cg_block<3, 2, 1, 272, 336>(Y, o1, tid);
    cg_block<2, 3, 1, 288, 336>(Y, o1, tid);
    cg_block<3, 3, 1, 320, 336>(Y, o1, tid);
    // J = 2, W = 384
    cg_block<1, 1, 2,  96, 384>(Y, o2, tid);
    cg_block<2, 1, 2, 144, 384>(Y, o2, tid);
    cg_block<3, 1, 2, 176, 384>(Y, o2, tid);
    cg_block<1, 2, 2, 192, 384>(Y, o2, tid);
    cg_block<2, 2, 2, 240, 384>(Y, o2, tid);
    cg_block<3, 2, 2, 272, 384>(Y, o2, tid);
    cg_block<1, 3, 2, 288, 384>(Y, o2, tid);
    cg_block<2, 3, 2, 336, 384>(Y, o2, tid);
    cg_block<3, 3, 2, 368, 384>(Y, o2, tid);
    // J = 3, W = 320
    cg_block<2, 1, 3,  80, 320>(Y, o3, tid);
    cg_block<3, 1, 3, 112, 320>(Y, o3, tid);
    cg_block<1, 2, 3, 128, 320>(Y, o3, tid);
    cg_block<2, 2, 3, 176, 320>(Y, o3, tid);
    cg_block<3, 2, 3, 208, 320>(Y, o3, tid);
    cg_block<1, 3, 3, 224, 320>(Y, o3, tid);
    cg_block<2, 3, 3, 272, 320>(Y, o3, tid);
    cg_block<3, 3, 3, 304, 320>(Y, o3, tid);
}

extern "C" void kernel_launch(void* const* d_in, const int* in_sizes, int n_in,
                              void* d_out, int out_size) {
    const float* x0   = (const float*)d_in[0];
    const float* x1   = (const float*)d_in[1];
    const float* x2   = (const float*)d_in[2];
    const float* x3   = (const float*)d_in[3];
    const int*   pidx = (const int*)d_in[4];
    const float* kern = (const float*)d_in[5];
    float* out = (float*)d_out;

    cg_precompute_kernel<<<64, 343>>>();
    shconv_kernel<<<NB * NV, THREADS>>>(x0, x1, x2, x3, pidx, kern, out);
}

// round 15
// speedup vs baseline: 1.8569x; 1.0311x over previous
#include <cuda_runtime.h>
#include <cstdint>

// Problem constants
#define NB 4
#define NN 4096
#define NV 2048
#define NP 32
// channel layout: c_off = {0,16,64,144}, total 256
// y rows: y_off = {0,4,13,23}, total 30
// output widths: W = {160, 336, 384, 320}
// output offsets (elements): 0, 1310720, 9568256, 25296896

// ---------------- CG tables (device-precomputed each launch, fp32) ----------------
// entries padded with {0,0} to a multiple of 4 so the kernel loop can unroll
__device__ int  d_nnz[64][7];
__device__ int2 d_voff[64][7][52];   // {smem offset, float bits}

struct cplxf { float re, im; };
__device__ __forceinline__ cplxf cmulf(cplxf a, cplxf b) {
    return { a.re * b.re - a.im * b.im, a.re * b.im + a.im * b.re };
}

__device__ float dfact_f(int n) { float r = 1.0f; for (int i = 2; i <= n; i++) r *= (float)i; return r; }

__device__ float su2cg_f(int j1, int m1, int j2, int m2, int j3, int m3) {
    if (m3 != m1 + m2) return 0.0f;
    int vmin = max(max(-j1 + j2 + m3, -j1 + m1), 0);
    int vmax = min(min(j2 + j3 + m1, j3 - j1 + j2), j3 + m3);
    float C = sqrtf((2.0f * j3 + 1.0f) * dfact_f(j3 + j1 - j2) * dfact_f(j3 - j1 + j2) * dfact_f(j1 + j2 - j3)
                    * dfact_f(j3 + m3) * dfact_f(j3 - m3)
                    / (dfact_f(j1 + j2 + j3 + 1) * dfact_f(j1 - m1) * dfact_f(j1 + m1)
                       * dfact_f(j2 - m2) * dfact_f(j2 + m2)));
    float S = 0.0f;
    for (int v = vmin; v <= vmax; v++) {
        float sgn = ((v + j2 + m2) & 1) ? -1.0f : 1.0f;
        S += sgn * dfact_f(j2 + j3 + m1 - v) * dfact_f(j1 - m1 + v)
             / (dfact_f(v) * dfact_f(j3 - j1 + j2 - v) * dfact_f(j3 + m3 - v) * dfact_f(v + j1 - j2 - m3));
    }
    return C * S;
}

// Q_{real->complex}(l)[r][c], includes the (-i)^l phase
__device__ cplxf qel_f(int l, int r, int c) {
    int m = r - l;
    const float s2 = 0.70710678118654752440f;
    float re = 0.f, im = 0.f;
    if (m == 0) { if (c == l) re = 1.0f; }
    else if (m < 0) {
        if (c == 2 * l - r) re = s2;        // col l+|m|
        else if (c == r)    im = -s2;       // col l-|m|
    } else {
        float sgn = (m & 1) ? -1.0f : 1.0f;
        if (c == r)             re = sgn * s2;   // col l+m
        else if (c == 2 * l - r) im = sgn * s2;  // col l-m
    }
    cplxf v{re, im};
    switch (l & 3) {  // multiply by (-i)^l
        case 1:  return {  v.im, -v.re };
        case 2:  return { -v.re, -v.im };
        case 3:  return { -v.im,  v.re };
        default: return v;
    }
}

__global__ void cg_precompute_kernel() {
    int bid = blockIdx.x;
    int j = (bid >> 4) & 3, l = (bid >> 2) & 3, J = bid & 3;
    int lo = (j > l) ? j - l : l - j;
    int hi = (j + l > 3) ? 3 : (j + l);
    if (j < 1 || l < 1 || J < lo || J > hi) return;

    __shared__ float cgs[7][7];
    __shared__ float creal[7][7][7];
    int tid = threadIdx.x;
    int nj = 2 * j + 1, nl = 2 * l + 1, nJ = 2 * J + 1;

    if (tid < nj * nl) {
        int i = tid / nl, k = tid - i * nl;
        int m1 = i - j, m2 = k - l, m3 = m1 + m2;
        cgs[i][k] = (m3 >= -J && m3 <= J) ? su2cg_f(j, m1, l, m2, J, m3) : 0.0f;
    }
    __syncthreads();

    int tot = nj * nl * nJ;
    if (tid < tot) {
        int p = tid % nJ; int t2 = tid / nJ;
        int b = t2 % nl;  int a = t2 / nl;
        float acc = 0.0f;
        for (int i = 0; i < nj; i++)
            for (int k = 0; k < nl; k++) {
                float c = cgs[i][k];
                if (c == 0.0f) continue;
                int n = (i - j) + (k - l) + J;          // complex m3 index in J block
                cplxf t = cmulf(qel_f(j, i, a), qel_f(l, k, b));
                cplxf q3 = qel_f(J, n, p); q3.im = -q3.im; // conj
                t = cmulf(t, q3);
                acc += t.re * c;
            }
        creal[a][b][p] = acc;
    }
    __syncthreads();

    const int yoff[4] = {0, 4, 13, 23};
    const int coff[4] = {0, 16, 64, 144};
    if (tid < nJ) {
        int pid = j * 16 + l * 4 + J;
        int cnt = 0;
        for (int a = 0; a < nj; a++)
            for (int b = 0; b < nl; b++) {
                float v = creal[a][b][tid];
                if (fabsf(v) > 1e-7f) {
                    // smem element offset of Y[y_off[j]+a*(4-j) (+i)][c_off[l]+b*16 (+cc)]
                    int off = (yoff[j] + a * (4 - j)) * 256 + coff[l] + b * 16;
                    d_voff[pid][tid][cnt] = make_int2(off, __float_as_int(v));
                    cnt++;
                }
            }
        // pad with {0, 0.0f} to a multiple of 4 (zero value contributes nothing;
        // offset 0 reads valid smem)
        while (cnt & 3) { d_voff[pid][tid][cnt] = make_int2(0, 0); cnt++; }
        d_nnz[pid][tid] = cnt;
    }
}

// ---------------- packed f32x2 helpers ----------------
__device__ __forceinline__ unsigned long long pack2(float x) {
    unsigned long long r; unsigned u = __float_as_uint(x);
    asm("mov.b64 %0, {%1, %1};" : "=l"(r) : "r"(u));
    return r;
}
__device__ __forceinline__ unsigned long long fma2(unsigned long long a, unsigned long long b,
                                                   unsigned long long c) {
    unsigned long long d;
    asm("fma.rn.f32x2 %0, %1, %2, %3;" : "=l"(d) : "l"(a), "l"(b), "l"(c));
    return d;
}
__device__ __forceinline__ void unpack2(unsigned long long v, float& x, float& y) {
    unsigned a, b;
    asm("mov.b64 {%0, %1}, %2;" : "=r"(a), "=r"(b) : "l"(v));
    x = __uint_as_float(a); y = __uint_as_float(b);
}

#define THREADS 128

// ---------------- stage-3 building blocks ----------------
// l==0 copy: out[j] block at channel 0: [n][i*16+cc] = Y[y_off[j]+n*(4-j)+i][cc]
template<int j, int W>
__device__ __forceinline__ void copy_l0(const float* Y, float* oJ, int tid) {
    constexpr int yo  = (j == 0 ? 0 : (j == 1 ? 4 : (j == 2 ? 13 : 23)));
    constexpr int nim = 4 - j;
    constexpr int nq  = (2 * j + 1) * nim * 4;   // float4 count
    for (int e = tid; e < nq; e += THREADS) {
        int n = e / (nim * 4);
        int r = e - n * (nim * 4);
        int i = r >> 2, q = r & 3;
        float4 v = *(const float4*)&Y[(yo + n * nim + i) * 256 + q * 4];
        *(float4*)&oJ[n * W + i * 16 + q * 4] = v;
    }
}
// j==0 copy: out[l] block: [m][i*16+cc] = Y[i][c_off[l]+m*16+cc]   (i in 0..3)
template<int l, int W, int CHOFF>
__device__ __forceinline__ void copy_j0(const float* Y, float* oJ, int tid) {
    constexpr int co = (l == 1 ? 16 : (l == 2 ? 64 : 144));
    constexpr int nq = (2 * l + 1) * 16;
    for (int e = tid; e < nq; e += THREADS) {
        int m = e >> 4, r = e & 15, i = r >> 2, q = r & 3;
        float4 v = *(const float4*)&Y[i * 256 + co + m * 16 + q * 4];
        *(float4*)&oJ[m * W + CHOFF + i * 16 + q * 4] = v;
    }
}
// CG block, float4-per-thread: out[pJ][i*16+cc4*4 .. +3] =
//   sum_k C_k * Y[off_k + i*256 + cc4*4 .. +3]
template<int j, int l, int J, int CHOFF, int W>
__device__ __forceinline__ void cg_block(const float* Y, float* oJ, int tid) {
    constexpr int pid   = j * 16 + l * 4 + J;
    constexpr int half4 = (4 - j) * 4;           // float4 elements per pJ row
    constexpr int ne    = (2 * J + 1) * half4;
    for (int e = tid; e < ne; e += THREADS) {
        int pJ = e / half4;
        int r  = e - pJ * half4;
        int add = (r >> 2) * 256 + (r & 3) * 4;  // i*256 + cc4*4
        int nnz = d_nnz[pid][pJ];                // multiple of 4 by construction
        const int2* tab = d_voff[pid][pJ];
        float ax = 0.f, ay = 0.f, az = 0.f, aw = 0.f;
#pragma unroll 4
        for (int k = 0; k < nnz; k++) {
            int2 vo = tab[k];
            float vv = __int_as_float(vo.y);
            float4 yv = *(const float4*)(Y + vo.x + add);
            ax = fmaf(vv, yv.x, ax);
            ay = fmaf(vv, yv.y, ay);
            az = fmaf(vv, yv.z, az);
            aw = fmaf(vv, yv.w, aw);
        }
        *(float4*)&oJ[pJ * W + CHOFF + (r >> 2) * 16 + (r & 3) * 4] =
            make_float4(ax, ay, az, aw);
    }
}

// ---------------- main kernel: one CTA per (b,v), 128 threads ----------------
__global__ void __launch_bounds__(THREADS) shconv_kernel(
    const float* __restrict__ x0, const float* __restrict__ x1,
    const float* __restrict__ x2, const float* __restrict__ x3,
    const int* __restrict__ pidx, const float* __restrict__ kern,
    float* __restrict__ out)
{
    __shared__ __align__(16) float Ksm[32 * 32];    // K rows padded 30 -> 32
    __shared__ __align__(16) float Gsm[32 * 256];   // reused as Y[30][256]
    __shared__ int rowid[32];

    int tid = threadIdx.x;
    int bv  = blockIdx.x;

    if (tid < 32) {
        int2 pi = ((const int2*)pidx)[(size_t)bv * 32 + tid];
        rowid[tid] = pi.x * NN + pi.y;
    }
    const float* kb = kern + (size_t)bv * 960;
    for (int i = tid; i < 960; i += THREADS) {
        int r = i / 30, c = i - r * 30;
        Ksm[r * 32 + c] = kb[i];
    }
    __syncthreads();

    // gather G: 32 rows x 256 floats = 2048 float4
    for (int e = tid; e < 2048; e += THREADS) {
        int p = e >> 6, f = e & 63;
        size_t r = (size_t)rowid[p];
        float4 v;
        if (f < 4)       v = ((const float4*)x0)[r * 4  + f];
        else if (f < 16) v = ((const float4*)x1)[r * 12 + (f - 4)];
        else if (f < 36) v = ((const float4*)x2)[r * 20 + (f - 16)];
        else             v = ((const float4*)x3)[r * 28 + (f - 36)];
        ((float4*)Gsm)[p * 64 + f] = v;
    }
    __syncthreads();

    // stage 1: Y(30x256) = K(32x30)^T G(32x256), f32x2 row-pair packed
    // thread owns cols {2*tid, 2*tid+1}; K rows read as 8x LDS.128
    unsigned long long accA[15], accB[15];
#pragma unroll
    for (int rp = 0; rp < 15; rp++) { accA[rp] = 0ull; accB[rp] = 0ull; }

    const float2* gcol = (const float2*)Gsm + tid;
#pragma unroll 2
    for (int p = 0; p < 32; p++) {
        float2 g = gcol[p * 128];
        unsigned long long ga = pack2(g.x), gb = pack2(g.y);
        const ulonglong2* kr = (const ulonglong2*)(Ksm + p * 32);
#pragma unroll
        for (int m = 0; m < 7; m++) {
            ulonglong2 kk = kr[m];                 // row pairs (4m,4m+1) and (4m+2,4m+3)
            accA[2 * m]     = fma2(kk.x, ga, accA[2 * m]);
            accB[2 * m]     = fma2(kk.x, gb, accB[2 * m]);
            accA[2 * m + 1] = fma2(kk.y, ga, accA[2 * m + 1]);
            accB[2 * m + 1] = fma2(kk.y, gb, accB[2 * m + 1]);
        }
        ulonglong2 kt = kr[7];                     // rows 28,29 (pad 30,31 unused)
        accA[14] = fma2(kt.x, ga, accA[14]);
        accB[14] = fma2(kt.x, gb, accB[14]);
    }
    __syncthreads();   // everyone done reading Gsm

    // write Y into Gsm: row 2rp -> (loA, loB), row 2rp+1 -> (hiA, hiB)
#pragma unroll
    for (int rp = 0; rp < 15; rp++) {
        float a0, a1, b0, b1;
        unpack2(accA[rp], a0, a1);
        unpack2(accB[rp], b0, b1);
        *(float2*)&Gsm[(2 * rp)     * 256 + 2 * tid] = make_float2(a0, b0);
        *(float2*)&Gsm[(2 * rp + 1) * 256 + 2 * tid] = make_float2(a1, b1);
    }
    __syncthreads();

    // stage 3: assemble outputs
    const float* Y = Gsm;
    float* o0 = out +               (size_t)bv * 160;
    float* o1 = out + 1310720u  +   (size_t)bv * 1008;   // 3*336
    float* o2 = out + 9568256u  +   (size_t)bv * 1920;   // 5*384
    float* o3 = out + 25296896u +   (size_t)bv * 2240;   // 7*320

    // direct copies
    copy_l0<0, 160>(Y, o0, tid);
    copy_l0<1, 336>(Y, o1, tid);
    copy_j0<1, 336, 48>(Y, o1, tid);
    copy_l0<2, 384>(Y, o2, tid);
    copy_j0<2, 384, 32>(Y, o2, tid);
    copy_l0<3, 320>(Y, o3, tid);
    copy_j0<3, 320, 16>(Y, o3, tid);

    // CG blocks (order/offsets match reference concatenation)
    // J = 0, W = 160
    cg_block<1, 1, 0,  64, 160>(Y, o0, tid);
    cg_block<2, 2, 0, 112, 160>(Y, o0, tid);
    cg_block<3, 3, 0, 144, 160>(Y, o0, tid);
    // J = 1, W = 336
    cg_block<1, 1, 1, 112, 336>(Y, o1, tid);
    cg_block<2, 1, 1, 160, 336>(Y, o1, tid);
    cg_block<1, 2, 1, 192, 336>(Y, o1, tid);
    cg_block<2, 2, 1, 240, 336>(Y, o1, tid);
    cg_block<3, 2, 1, 272, 336>(Y, o1, tid);
    cg_block<2, 3, 1, 288, 336>(Y, o1, tid);
    cg_block<3, 3, 1, 320, 336>(Y, o1, tid);
    // J = 2, W = 384
    cg_block<1, 1, 2,  96, 384>(Y, o2, tid);
    cg_block<2, 1, 2, 144, 384>(Y, o2, tid);
    cg_block<3, 1, 2, 176, 384>(Y, o2, tid);
    cg_block<1, 2, 2, 192, 384>(Y, o2, tid);
    cg_block<2, 2, 2, 240, 384>(Y, o2, tid);
    cg_block<3, 2, 2, 272, 384>(Y, o2, tid);
    cg_block<1, 3, 2, 288, 384>(Y, o2, tid);
    cg_block<2, 3, 2, 336, 384>(Y, o2, tid);
    cg_block<3, 3, 2, 368, 384>(Y, o2, tid);
    // J = 3, W = 320
    cg_block<2, 1, 3,  80, 320>(Y, o3, tid);
    cg_block<3, 1, 3, 112, 320>(Y, o3, tid);
    cg_block<1, 2, 3, 128, 320>(Y, o3, tid);
    cg_block<2, 2, 3, 176, 320>(Y, o3, tid);
    cg_block<3, 2, 3, 208, 320>(Y, o3, tid);
    cg_block<1, 3, 3, 224, 320>(Y, o3, tid);
    cg_block<2, 3, 3, 272, 320>(Y, o3, tid);
    cg_block<3, 3, 3, 304, 320>(Y, o3, tid);
}

extern "C" void kernel_launch(void* const* d_in, const int* in_sizes, int n_in,
                              void* d_out, int out_size) {
    const float* x0   = (const float*)d_in[0];
    const float* x1   = (const float*)d_in[1];
    const float* x2   = (const float*)d_in[2];
    const float* x3   = (const float*)d_in[3];
    const int*   pidx = (const int*)d_in[4];
    const float* kern = (const float*)d_in[5];
    float* out = (float*)d_out;

    cg_precompute_kernel<<<64, 343>>>();
    shconv_kernel<<<NB * NV, THREADS>>>(x0, x1, x2, x3, pidx, kern, out);
}

// round 17
// speedup vs baseline: 2.1951x; 1.1821x over previous
#include <cuda_runtime.h>
#include <cstdint>

// Problem constants
#define NB 4
#define NN 4096
#define NV 2048
#define NP 32
// channel layout: c_off = {0,16,64,144}, total 256
// y rows: y_off = {0,4,13,23}, total 30
// output widths: W = {160, 336, 384, 320}
// output offsets (elements): 0, 1310720, 9568256, 25296896

// ---------------- CG tables (device-precomputed each launch, fp32) ----------------
// entries padded with {0,0} to a multiple of 4 so the kernel loop can unroll
__device__ int  d_nnz[64][7];
__device__ int2 d_voff[64][7][52];   // {smem offset, float bits}

// ---------------- flattened stage-3 worklist ----------------
// one item per output float4: 360 copies + 972 cg outputs = 1332
#define NWORK 1332
__device__ int4 d_work[NWORK];

// 34 blocks: 7 copies (type 0 = l0-copy, 1 = j0-copy) then 27 cg (type 2)
__device__ const short       wk_start[35] = {0,16,52,100,140,220,248,360,372,380,384,420,444,480,504,516,540,552,612,652,672,732,772,792,852,892,912,968,996,1080,1136,1164,1248,1304,1332};
__device__ const signed char wk_type[34]  = {0,0,1,0,1,0,1, 2,2,2, 2,2,2,2,2,2,2, 2,2,2,2,2,2,2,2,2, 2,2,2,2,2,2,2,2};
__device__ const signed char wk_p1[34]    = {0,1,1,2,2,3,3, 1,2,3, 1,2,1,2,3,2,3, 1,2,3,1,2,3,1,2,3, 2,3,1,2,3,1,2,3};          // j (l0/cg) or l (j0)
__device__ const short       wk_p2[34]    = {0,0,16,0,64,0,144, 1,2,3, 1,1,2,2,2,3,3, 1,1,1,2,2,2,3,3,3, 1,1,2,2,2,3,3,3};      // co (j0) or l (cg)
__device__ const signed char wk_J[34]     = {0,0,0,0,0,0,0, 0,0,0, 1,1,1,1,1,1,1, 2,2,2,2,2,2,2,2,2, 3,3,3,3,3,3,3,3};
__device__ const short       wk_CH[34]    = {0,0,48,0,32,0,16, 64,112,144, 112,160,192,240,272,288,320, 96,144,176,192,240,272,288,336,368, 80,112,128,176,208,224,272,304};
__device__ const short       wk_W[34]     = {160,336,336,384,384,320,320, 160,160,160, 336,336,336,336,336,336,336, 384,384,384,384,384,384,384,384,384, 320,320,320,320,320,320,320,320};
__device__ const signed char wk_sec[34]   = {0,1,1,2,2,3,3, 0,0,0, 1,1,1,1,1,1,1, 2,2,2,2,2,2,2,2,2, 3,3,3,3,3,3,3,3};

__global__ void build_worklist_kernel() {
    int w = blockIdx.x * blockDim.x + threadIdx.x;
    if (w >= NWORK) return;
    int b = 0;
    while (w >= wk_start[b + 1]) b++;
    int t   = w - wk_start[b];
    int typ = wk_type[b];
    int W   = wk_W[b], CH = wk_CH[b], sec = wk_sec[b];
    int add, dstoff, grp;
    if (typ == 0) {                       // l==0 copy, j = p1
        int j  = wk_p1[b];
        int yo = (j == 0 ? 0 : (j == 1 ? 4 : (j == 2 ? 13 : 23)));
        int nim = 4 - j;
        int n = t / (nim * 4);
        int r = t - n * nim * 4;
        int i = r >> 2, q = r & 3;
        add    = (yo + n * nim + i) * 256 + q * 4;
        dstoff = n * W + i * 16 + q * 4;
        grp    = -1;
    } else if (typ == 1) {                // j==0 copy, co = p2
        int co = wk_p2[b];
        int m = t >> 4, r = t & 15, i = r >> 2, q = r & 3;
        add    = i * 256 + co + m * 16 + q * 4;
        dstoff = m * W + CH + i * 16 + q * 4;
        grp    = -1;
    } else {                              // cg block: j=p1, l=p2, J
        int j = wk_p1[b], l = wk_p2[b], J = wk_J[b];
        int half4 = (4 - j) * 4;
        int pJ = t / half4;
        int r  = t - pJ * half4;
        int i = r >> 2, q = r & 3;
        add    = i * 256 + q * 4;
        dstoff = pJ * W + CH + i * 16 + q * 4;
        grp    = (j * 16 + l * 4 + J) * 7 + pJ;
    }
    d_work[w] = make_int4((sec << 20) | dstoff, add, grp, 0);
}

// ---------------- CG coefficient precompute (fp32) ----------------
struct cplxf { float re, im; };
__device__ __forceinline__ cplxf cmulf(cplxf a, cplxf b) {
    return { a.re * b.re - a.im * b.im, a.re * b.im + a.im * b.re };
}

__device__ float dfact_f(int n) { float r = 1.0f; for (int i = 2; i <= n; i++) r *= (float)i; return r; }

__device__ float su2cg_f(int j1, int m1, int j2, int m2, int j3, int m3) {
    if (m3 != m1 + m2) return 0.0f;
    int vmin = max(max(-j1 + j2 + m3, -j1 + m1), 0);
    int vmax = min(min(j2 + j3 + m1, j3 - j1 + j2), j3 + m3);
    float C = sqrtf((2.0f * j3 + 1.0f) * dfact_f(j3 + j1 - j2) * dfact_f(j3 - j1 + j2) * dfact_f(j1 + j2 - j3)
                    * dfact_f(j3 + m3) * dfact_f(j3 - m3)
                    / (dfact_f(j1 + j2 + j3 + 1) * dfact_f(j1 - m1) * dfact_f(j1 + m1)
                       * dfact_f(j2 - m2) * dfact_f(j2 + m2)));
    float S = 0.0f;
    for (int v = vmin; v <= vmax; v++) {
        float sgn = ((v + j2 + m2) & 1) ? -1.0f : 1.0f;
        S += sgn * dfact_f(j2 + j3 + m1 - v) * dfact_f(j1 - m1 + v)
             / (dfact_f(v) * dfact_f(j3 - j1 + j2 - v) * dfact_f(j3 + m3 - v) * dfact_f(v + j1 - j2 - m3));
    }
    return C * S;
}

// Q_{real->complex}(l)[r][c], includes the (-i)^l phase
__device__ cplxf qel_f(int l, int r, int c) {
    int m = r - l;
    const float s2 = 0.70710678118654752440f;
    float re = 0.f, im = 0.f;
    if (m == 0) { if (c == l) re = 1.0f; }
    else if (m < 0) {
        if (c == 2 * l - r) re = s2;        // col l+|m|
        else if (c == r)    im = -s2;       // col l-|m|
    } else {
        float sgn = (m & 1) ? -1.0f : 1.0f;
        if (c == r)             re = sgn * s2;   // col l+m
        else if (c == 2 * l - r) im = sgn * s2;  // col l-m
    }
    cplxf v{re, im};
    switch (l & 3) {  // multiply by (-i)^l
        case 1:  return {  v.im, -v.re };
        case 2:  return { -v.re, -v.im };
        case 3:  return { -v.im,  v.re };
        default: return v;
    }
}

__global__ void cg_precompute_kernel() {
    int bid = blockIdx.x;
    int j = (bid >> 4) & 3, l = (bid >> 2) & 3, J = bid & 3;
    int lo = (j > l) ? j - l : l - j;
    int hi = (j + l > 3) ? 3 : (j + l);
    if (j < 1 || l < 1 || J < lo || J > hi) return;

    __shared__ float cgs[7][7];
    __shared__ float creal[7][7][7];
    int tid = threadIdx.x;
    int nj = 2 * j + 1, nl = 2 * l + 1, nJ = 2 * J + 1;

    if (tid < nj * nl) {
        int i = tid / nl, k = tid - i * nl;
        int m1 = i - j, m2 = k - l, m3 = m1 + m2;
        cgs[i][k] = (m3 >= -J && m3 <= J) ? su2cg_f(j, m1, l, m2, J, m3) : 0.0f;
    }
    __syncthreads();

    int tot = nj * nl * nJ;
    if (tid < tot) {
        int p = tid % nJ; int t2 = tid / nJ;
        int b = t2 % nl;  int a = t2 / nl;
        float acc = 0.0f;
        for (int i = 0; i < nj; i++)
            for (int k = 0; k < nl; k++) {
                float c = cgs[i][k];
                if (c == 0.0f) continue;
                int n = (i - j) + (k - l) + J;          // complex m3 index in J block
                cplxf t = cmulf(qel_f(j, i, a), qel_f(l, k, b));
                cplxf q3 = qel_f(J, n, p); q3.im = -q3.im; // conj
                t = cmulf(t, q3);
                acc += t.re * c;
            }
        creal[a][b][p] = acc;
    }
    __syncthreads();

    const int yoff[4] = {0, 4, 13, 23};
    const int coff[4] = {0, 16, 64, 144};
    if (tid < nJ) {
        int pid = j * 16 + l * 4 + J;
        int cnt = 0;
        for (int a = 0; a < nj; a++)
            for (int b = 0; b < nl; b++) {
                float v = creal[a][b][tid];
                if (fabsf(v) > 1e-7f) {
                    // smem element offset of Y[y_off[j]+a*(4-j) (+i)][c_off[l]+b*16 (+cc)]
                    int off = (yoff[j] + a * (4 - j)) * 256 + coff[l] + b * 16;
                    d_voff[pid][tid][cnt] = make_int2(off, __float_as_int(v));
                    cnt++;
                }
            }
        // pad with {0, 0.0f} to a multiple of 4 (zero value contributes nothing;
        // offset 0 reads valid smem)
        while (cnt & 3) { d_voff[pid][tid][cnt] = make_int2(0, 0); cnt++; }
        d_nnz[pid][tid] = cnt;
    }
}

// ---------------- packed f32x2 helpers ----------------
__device__ __forceinline__ unsigned long long pack2(float x) {
    unsigned long long r; unsigned u = __float_as_uint(x);
    asm("mov.b64 %0, {%1, %1};" : "=l"(r) : "r"(u));
    return r;
}
__device__ __forceinline__ unsigned long long fma2(unsigned long long a, unsigned long long b,
                                                   unsigned long long c) {
    unsigned long long d;
    asm("fma.rn.f32x2 %0, %1, %2, %3;" : "=l"(d) : "l"(a), "l"(b), "l"(c));
    return d;
}
__device__ __forceinline__ void unpack2(unsigned long long v, float& x, float& y) {
    unsigned a, b;
    asm("mov.b64 {%0, %1}, %2;" : "=r"(a), "=r"(b) : "l"(v));
    x = __uint_as_float(a); y = __uint_as_float(b);
}

#define THREADS 128

// ---------------- main kernel: one CTA per (b,v), 128 threads ----------------
__global__ void __launch_bounds__(THREADS) shconv_kernel(
    const float* __restrict__ x0, const float* __restrict__ x1,
    const float* __restrict__ x2, const float* __restrict__ x3,
    const int* __restrict__ pidx, const float* __restrict__ kern,
    float* __restrict__ out)
{
    __shared__ __align__(16) float Ksm[32 * 32];    // K rows padded 30 -> 32
    __shared__ __align__(16) float Gsm[32 * 256];   // reused as Y[30][256]
    __shared__ int rowid[32];

    int tid = threadIdx.x;
    int bv  = blockIdx.x;

    if (tid < 32) {
        int2 pi = ((const int2*)pidx)[(size_t)bv * 32 + tid];
        rowid[tid] = pi.x * NN + pi.y;
    }
    const float* kb = kern + (size_t)bv * 960;
    for (int i = tid; i < 960; i += THREADS) {
        int r = i / 30, c = i - r * 30;
        Ksm[r * 32 + c] = kb[i];
    }
    __syncthreads();

    // gather G: 32 rows x 256 floats = 2048 float4
    for (int e = tid; e < 2048; e += THREADS) {
        int p = e >> 6, f = e & 63;
        size_t r = (size_t)rowid[p];
        float4 v;
        if (f < 4)       v = ((const float4*)x0)[r * 4  + f];
        else if (f < 16) v = ((const float4*)x1)[r * 12 + (f - 4)];
        else if (f < 36) v = ((const float4*)x2)[r * 20 + (f - 16)];
        else             v = ((const float4*)x3)[r * 28 + (f - 36)];
        ((float4*)Gsm)[p * 64 + f] = v;
    }
    __syncthreads();

    // stage 1: Y(30x256) = K(32x30)^T G(32x256), f32x2 row-pair packed
    // thread owns cols {2*tid, 2*tid+1}; K rows read as 8x LDS.128
    unsigned long long accA[15], accB[15];
#pragma unroll
    for (int rp = 0; rp < 15; rp++) { accA[rp] = 0ull; accB[rp] = 0ull; }

    const float2* gcol = (const float2*)Gsm + tid;
#pragma unroll 2
    for (int p = 0; p < 32; p++) {
        float2 g = gcol[p * 128];
        unsigned long long ga = pack2(g.x), gb = pack2(g.y);
        const ulonglong2* kr = (const ulonglong2*)(Ksm + p * 32);
#pragma unroll
        for (int m = 0; m < 7; m++) {
            ulonglong2 kk = kr[m];                 // row pairs (4m,4m+1) and (4m+2,4m+3)
            accA[2 * m]     = fma2(kk.x, ga, accA[2 * m]);
            accB[2 * m]     = fma2(kk.x, gb, accB[2 * m]);
            accA[2 * m + 1] = fma2(kk.y, ga, accA[2 * m + 1]);
            accB[2 * m + 1] = fma2(kk.y, gb, accB[2 * m + 1]);
        }
        ulonglong2 kt = kr[7];                     // rows 28,29 (pad 30,31 unused)
        accA[14] = fma2(kt.x, ga, accA[14]);
        accB[14] = fma2(kt.x, gb, accB[14]);
    }
    __syncthreads();   // everyone done reading Gsm

    // write Y into Gsm: row 2rp -> (loA, loB), row 2rp+1 -> (hiA, hiB)
#pragma unroll
    for (int rp = 0; rp < 15; rp++) {
        float a0, a1, b0, b1;
        unpack2(accA[rp], a0, a1);
        unpack2(accB[rp], b0, b1);
        *(float2*)&Gsm[(2 * rp)     * 256 + 2 * tid] = make_float2(a0, b0);
        *(float2*)&Gsm[(2 * rp + 1) * 256 + 2 * tid] = make_float2(a1, b1);
    }
    __syncthreads();

    // stage 3: flattened worklist — one item per output float4
    const float* Y = Gsm;
    float* o0 = out +               (size_t)bv * 160;
    float* o1 = out + 1310720u  +   (size_t)bv * 1008;   // 3*336
    float* o2 = out + 9568256u  +   (size_t)bv * 1920;   // 5*384
    float* o3 = out + 25296896u +   (size_t)bv * 2240;   // 7*320

    const int4* wk = d_work;
    const int*  nz = (const int*)d_nnz;
    const int2* tb = &d_voff[0][0][0];
    for (int w = tid; w < NWORK; w += THREADS) {
        int4 it = wk[w];
        int sec = it.x >> 20;
        int off = it.x & 0xFFFFF;
        float* dst = (sec == 0 ? o0 : sec == 1 ? o1 : sec == 2 ? o2 : o3) + off;
        if (it.z < 0) {                       // direct copy
            *(float4*)dst = *(const float4*)(Y + it.y);
        } else {                              // cg accumulation
            int nnz = nz[it.z];               // multiple of 4
            const int2* tab = tb + it.z * 52;
            float ax = 0.f, ay = 0.f, az = 0.f, aw = 0.f;
#pragma unroll 4
            for (int k = 0; k < nnz; k++) {
                int2 vo = tab[k];
                float vv = __int_as_float(vo.y);
                float4 yv = *(const float4*)(Y + vo.x + it.y);
                ax = fmaf(vv, yv.x, ax);
                ay = fmaf(vv, yv.y, ay);
                az = fmaf(vv, yv.z, az);
                aw = fmaf(vv, yv.w, aw);
            }
            *(float4*)dst = make_float4(ax, ay, az, aw);
        }
    }
}

extern "C" void kernel_launch(void* const* d_in, const int* in_sizes, int n_in,
                              void* d_out, int out_size) {
    const float* x0   = (const float*)d_in[0];
    const float* x1   = (const float*)d_in[1];
    const float* x2   = (const float*)d_in[2];
    const float* x3   = (const float*)d_in[3];
    const int*   pidx = (const int*)d_in[4];
    const float* kern = (const float*)d_in[5];
    float* out = (float*)d_out;

    cg_precompute_kernel<<<64, 343>>>();
    build_worklist_kernel<<<(NWORK + 127) / 128, 128>>>();
    shconv_kernel<<<NB * NV, THREADS>>>(x0, x1, x2, x3, pidx, kern, out);
}